// round 2
// baseline (speedup 1.0000x reference)
#include <cuda_runtime.h>
#include <cstddef>

#define NP 4
#define NS 4
#define NC 64
#define NF 64
#define NB 64
// PS = 16, PSC = 1024, per-psc KQ block = F*C*F = 262144 floats

__device__ float g_scores[NP * NS * NC * NC];   // 65536
__device__ float g_weights[NP * NS * NC * NC];  // softmax(scores)

// ---------------------------------------------------------------------------
// Kernel A: scores[psc][d] = sum_{f,g} KQ[psc][f][d][g]
// One block per psc (1024 blocks), 1024 threads.
// Thread t: d = t>>4, j = t&15 -> owns g-range [4j, 4j+4) as a float4,
// loops over f with stride C*F floats. Fully coalesced (warp covers a
// contiguous 512B span per f iteration).
// ---------------------------------------------------------------------------
__global__ void __launch_bounds__(1024, 2)
reduce_scores_kernel(const float* __restrict__ kq) {
    const int psc = blockIdx.x;
    const int t   = threadIdx.x;
    const int d   = t >> 4;
    const int j   = t & 15;

    const float4* base =
        reinterpret_cast<const float4*>(kq + (size_t)psc * (NF * NC * NF))
        + (d * (NF / 4) + j);                 // (d*F + 4j)/4 float4s

    float4 acc = make_float4(0.f, 0.f, 0.f, 0.f);
#pragma unroll 4
    for (int f = 0; f < NF; ++f) {
        float4 v = base[f * (NC * NF / 4)];
        acc.x += v.x; acc.y += v.y; acc.z += v.z; acc.w += v.w;
    }
    float s = (acc.x + acc.y) + (acc.z + acc.w);

    // reduce across the 16 lanes that share this d (lanes j=0..15 are
    // contiguous within a half-warp; xor 8,4,2,1 stays inside the group)
    s += __shfl_xor_sync(0xffffffffu, s, 8);
    s += __shfl_xor_sync(0xffffffffu, s, 4);
    s += __shfl_xor_sync(0xffffffffu, s, 2);
    s += __shfl_xor_sync(0xffffffffu, s, 1);

    if (j == 0) g_scores[psc * NC + d] = s;
}

// ---------------------------------------------------------------------------
// Kernel B: row-wise softmax over d (rows = psc, length C=64).
// 1024 blocks x 32 threads, each thread handles 2 elements.
// ---------------------------------------------------------------------------
__global__ void softmax_kernel() {
    const int psc  = blockIdx.x;
    const int lane = threadIdx.x;
    const float a = g_scores[psc * NC + lane];
    const float b = g_scores[psc * NC + lane + 32];

    float m = fmaxf(a, b);
#pragma unroll
    for (int off = 16; off > 0; off >>= 1)
        m = fmaxf(m, __shfl_xor_sync(0xffffffffu, m, off));

    const float ea = __expf(a - m);
    const float eb = __expf(b - m);
    float s = ea + eb;
#pragma unroll
    for (int off = 16; off > 0; off >>= 1)
        s += __shfl_xor_sync(0xffffffffu, s, off);

    const float inv = 1.0f / s;
    g_weights[psc * NC + lane]      = ea * inv;
    g_weights[psc * NC + lane + 32] = eb * inv;
}

// ---------------------------------------------------------------------------
// Kernel C: fused V = X @ Wv^T and out = w @ V per (b, ps).
// 1024 blocks (b*16 + ps), 256 threads.
// Thread (tc = t>>4, tf = t&15) computes a 4x4 register tile with
// STRIDED tiling: c in {tc, tc+16, tc+32, tc+48}, f in {tf, tf+16, ...}.
// With [64][65] smem padding the Wv/Vs column reads (lane-varying f,
// stride-16) hit 16 distinct banks -> conflict-free.
// ---------------------------------------------------------------------------
__global__ void __launch_bounds__(256)
fused_attn_kernel(const float* __restrict__ x,
                  const float* __restrict__ wv,
                  float* __restrict__ out) {
    __shared__ float bufA[NC][NF + 1];  // X tile -> then V tile
    __shared__ float bufB[NF][NF + 1];  // Wv     -> then softmax weights

    const int blk = blockIdx.x;
    const int b   = blk >> 4;          // 0..63
    const int ps  = blk & 15;          // 0..15
    const int t   = threadIdx.x;
    const int tc  = t >> 4;            // 0..15
    const int tf  = t & 15;            // 0..15

    // --- load X[b, ps, :, :] (4096 contiguous floats) and Wv (4096) ---
    const float* xsrc = x + ((size_t)b * (NP * NS * NC * NF) + (size_t)ps * (NC * NF));
#pragma unroll
    for (int r = 0; r < 16; ++r) {
        int idx = t + r * 256;
        bufA[idx >> 6][idx & 63] = xsrc[idx];
        bufB[idx >> 6][idx & 63] = wv[idx];
    }
    __syncthreads();

    // --- GEMM 1: V[c][f] = sum_k X[c][k] * Wv[f][k] ---
    float v[4][4];
#pragma unroll
    for (int i = 0; i < 4; ++i)
#pragma unroll
        for (int jj = 0; jj < 4; ++jj) v[i][jj] = 0.f;

#pragma unroll 4
    for (int k = 0; k < NF; ++k) {
        float xr[4], wr[4];
#pragma unroll
        for (int i = 0; i < 4; ++i) xr[i] = bufA[tc + 16 * i][k];
#pragma unroll
        for (int jj = 0; jj < 4; ++jj) wr[jj] = bufB[tf + 16 * jj][k];
#pragma unroll
        for (int i = 0; i < 4; ++i)
#pragma unroll
            for (int jj = 0; jj < 4; ++jj) v[i][jj] += xr[i] * wr[jj];
    }
    __syncthreads();  // all reads of bufA/bufB complete

    // --- write V into bufA, load softmax weights into bufB ---
#pragma unroll
    for (int i = 0; i < 4; ++i)
#pragma unroll
        for (int jj = 0; jj < 4; ++jj)
            bufA[tc + 16 * i][tf + 16 * jj] = v[i][jj];

    const float* wsrc = g_weights + (size_t)ps * (NC * NC);
#pragma unroll
    for (int r = 0; r < 16; ++r) {
        int idx = t + r * 256;
        bufB[idx >> 6][idx & 63] = wsrc[idx];  // w[c][d]
    }
    __syncthreads();

    // --- GEMM 2: out[c][f] = sum_d w[c][d] * V[d][f] ---
    float o[4][4];
#pragma unroll
    for (int i = 0; i < 4; ++i)
#pragma unroll
        for (int jj = 0; jj < 4; ++jj) o[i][jj] = 0.f;

#pragma unroll 4
    for (int dd = 0; dd < NC; ++dd) {
        float cr[4], vr[4];
#pragma unroll
        for (int i = 0; i < 4; ++i) cr[i] = bufB[tc + 16 * i][dd];
#pragma unroll
        for (int jj = 0; jj < 4; ++jj) vr[jj] = bufA[dd][tf + 16 * jj];
#pragma unroll
        for (int i = 0; i < 4; ++i)
#pragma unroll
            for (int jj = 0; jj < 4; ++jj) o[i][jj] += cr[i] * vr[jj];
    }

    // --- store: out[c, b, ps*F + f] ---
#pragma unroll
    for (int i = 0; i < 4; ++i) {
        const int c = tc + 16 * i;
        float* orow = out + ((size_t)c * NB + b) * (NP * NS * NF) + (size_t)ps * NF;
#pragma unroll
        for (int jj = 0; jj < 4; ++jj) {
            orow[tf + 16 * jj] = o[i][jj];
        }
    }
}

// ---------------------------------------------------------------------------
extern "C" void kernel_launch(void* const* d_in, const int* in_sizes, int n_in,
                              void* d_out, int out_size) {
    const float* X  = (const float*)d_in[0];  // (B, P*S*C*F)
    const float* KQ = (const float*)d_in[1];  // (P,S,C,F,C,F) — 1 GB
    const float* Wv = (const float*)d_in[2];  // (F, F)
    float* out = (float*)d_out;               // (C, B, P*S*F)

    reduce_scores_kernel<<<NP * NS * NC, 1024>>>(KQ);
    softmax_kernel<<<NP * NS * NC, 32>>>();
    fused_attn_kernel<<<NB * NP * NS, 256>>>(X, Wv, out);
}

// round 3
// speedup vs baseline: 1.0721x; 1.0721x over previous
#include <cuda_runtime.h>
#include <cstddef>

#define NP 4
#define NS 4
#define NC 64
#define NF 64
#define NB 64
// PS = 16, PSC = 1024, per-psc KQ block = F*C*F = 262144 floats

__device__ float g_weights[NP * NS * NC * NC];           // softmax(scores), 256 KB
__device__ float g_V[NB * NP * NS * NC * NF];            // V = X @ Wv^T, 16 MB

// ---------------------------------------------------------------------------
// Combined kernel: 2048 blocks x 1024 threads, roles interleaved by bid&1.
//
// EVEN blocks (psc = bid>>1, 0..1023):
//   scores[psc][d] = sum_{f,g} KQ[psc][f][d][g], then softmax over d fused
//   in the epilogue (the block owns the whole 64-wide row).
//   Thread t: d = t>>4, j = t&15 owns float4 g-range [4j,4j+4), loops over f
//   (stride C*F). Fully coalesced; __ldcs since KQ is stream-once.
//
// ODD blocks (bp = bid>>1 = b*16+ps, 0..1023):
//   V[bp][c][f] = sum_k X[bp][c][k] * Wv[f][k]  (64x64x64 smem GEMM,
//   2x2 register tile, stride-32). This work is independent of KQ and hides
//   in the ~91% idle issue slots of the DRAM-bound reduce blocks.
// ---------------------------------------------------------------------------
__global__ void __launch_bounds__(1024, 2)
reduce_softmax_v_kernel(const float* __restrict__ kq,
                        const float* __restrict__ x,
                        const float* __restrict__ wv) {
    __shared__ float sh[2 * NC * (NF + 1)];  // 33.3 KB, shared by both roles

    const int bid = blockIdx.x;
    const int t   = threadIdx.x;

    if ((bid & 1) == 0) {
        // ---- role A: KQ reduction + softmax ----
        const int psc = bid >> 1;
        const int d   = t >> 4;
        const int j   = t & 15;

        const float4* base =
            reinterpret_cast<const float4*>(kq + (size_t)psc * (NF * NC * NF))
            + (d * (NF / 4) + j);

        float4 acc = make_float4(0.f, 0.f, 0.f, 0.f);
#pragma unroll 4
        for (int f = 0; f < NF; ++f) {
            float4 v = __ldcs(base + f * (NC * NF / 4));
            acc.x += v.x; acc.y += v.y; acc.z += v.z; acc.w += v.w;
        }
        float s = (acc.x + acc.y) + (acc.z + acc.w);

        s += __shfl_xor_sync(0xffffffffu, s, 8);
        s += __shfl_xor_sync(0xffffffffu, s, 4);
        s += __shfl_xor_sync(0xffffffffu, s, 2);
        s += __shfl_xor_sync(0xffffffffu, s, 1);

        if (j == 0) sh[d] = s;
        __syncthreads();

        // fused softmax over the 64 scores, one warp
        if (t < 32) {
            const float a = sh[t];
            const float b = sh[t + 32];
            float m = fmaxf(a, b);
#pragma unroll
            for (int off = 16; off > 0; off >>= 1)
                m = fmaxf(m, __shfl_xor_sync(0xffffffffu, m, off));
            const float ea = __expf(a - m);
            const float eb = __expf(b - m);
            float ssum = ea + eb;
#pragma unroll
            for (int off = 16; off > 0; off >>= 1)
                ssum += __shfl_xor_sync(0xffffffffu, ssum, off);
            const float inv = 1.0f / ssum;
            g_weights[psc * NC + t]      = ea * inv;
            g_weights[psc * NC + t + 32] = eb * inv;
        }
    } else {
        // ---- role B: V = X @ Wv^T for one (b,ps) ----
        const int bp = bid >> 1;                    // = b*16 + ps
        float* bufX = sh;                           // [64][65]
        float* bufW = sh + NC * (NF + 1);           // [64][65]

        const float* xsrc = x + (size_t)bp * (NC * NF);
#pragma unroll
        for (int r = 0; r < 4; ++r) {
            const int idx = t + r * 1024;
            bufX[(idx >> 6) * (NF + 1) + (idx & 63)] = xsrc[idx];
            bufW[(idx >> 6) * (NF + 1) + (idx & 63)] = wv[idx];
        }
        __syncthreads();

        const int tc = t >> 5;   // 0..31 (constant within a warp -> broadcasts)
        const int tf = t & 31;   // 0..31 (stride-65 rows -> conflict-free)
        float v00 = 0.f, v01 = 0.f, v10 = 0.f, v11 = 0.f;
#pragma unroll 4
        for (int k = 0; k < NF; ++k) {
            const float x0 = bufX[tc        * (NF + 1) + k];
            const float x1 = bufX[(tc + 32) * (NF + 1) + k];
            const float w0 = bufW[tf        * (NF + 1) + k];
            const float w1 = bufW[(tf + 32) * (NF + 1) + k];
            v00 += x0 * w0; v01 += x0 * w1;
            v10 += x1 * w0; v11 += x1 * w1;
        }

        float* vdst = g_V + (size_t)bp * (NC * NF);
        vdst[tc        * NF + tf]      = v00;
        vdst[tc        * NF + tf + 32] = v01;
        vdst[(tc + 32) * NF + tf]      = v10;
        vdst[(tc + 32) * NF + tf + 32] = v11;
    }
}

// ---------------------------------------------------------------------------
// Kernel 2: out[b,ps][c][f] = sum_d w[ps][c][d] * V[b,ps][d][f]
// 1024 blocks (b*16+ps) x 256 threads, 4x4 register tile, stride-16.
// ---------------------------------------------------------------------------
__global__ void __launch_bounds__(256)
attn_out_kernel(float* __restrict__ out) {
    __shared__ float bufV[NC][NF + 1];
    __shared__ float bufW[NC][NF + 1];

    const int blk = blockIdx.x;
    const int b   = blk >> 4;
    const int ps  = blk & 15;
    const int t   = threadIdx.x;
    const int tc  = t >> 4;
    const int tf  = t & 15;

    const float* vsrc = g_V + (size_t)blk * (NC * NF);
    const float* wsrc = g_weights + (size_t)ps * (NC * NC);
#pragma unroll
    for (int r = 0; r < 16; ++r) {
        const int idx = t + r * 256;
        bufV[idx >> 6][idx & 63] = vsrc[idx];
        bufW[idx >> 6][idx & 63] = wsrc[idx];   // w[c][d]
    }
    __syncthreads();

    float o[4][4];
#pragma unroll
    for (int i = 0; i < 4; ++i)
#pragma unroll
        for (int jj = 0; jj < 4; ++jj) o[i][jj] = 0.f;

#pragma unroll 4
    for (int dd = 0; dd < NC; ++dd) {
        float cr[4], vr[4];
#pragma unroll
        for (int i = 0; i < 4; ++i)  cr[i]  = bufW[tc + 16 * i][dd];
#pragma unroll
        for (int jj = 0; jj < 4; ++jj) vr[jj] = bufV[dd][tf + 16 * jj];
#pragma unroll
        for (int i = 0; i < 4; ++i)
#pragma unroll
            for (int jj = 0; jj < 4; ++jj) o[i][jj] += cr[i] * vr[jj];
    }

    // out layout: (C, B, P*S*F); out[c, b, ps*F + f]
#pragma unroll
    for (int i = 0; i < 4; ++i) {
        const int c = tc + 16 * i;
        float* orow = out + ((size_t)c * NB + b) * (NP * NS * NF) + (size_t)ps * NF;
#pragma unroll
        for (int jj = 0; jj < 4; ++jj) {
            orow[tf + 16 * jj] = o[i][jj];
        }
    }
}

// ---------------------------------------------------------------------------
extern "C" void kernel_launch(void* const* d_in, const int* in_sizes, int n_in,
                              void* d_out, int out_size) {
    const float* X  = (const float*)d_in[0];  // (B, P*S*C*F)
    const float* KQ = (const float*)d_in[1];  // (P,S,C,F,C,F) — 1 GB
    const float* Wv = (const float*)d_in[2];  // (F, F)
    float* out = (float*)d_out;               // (C, B, P*S*F)

    reduce_softmax_v_kernel<<<2 * NP * NS * NC * NC / NC * 1, 1024>>>(KQ, X, Wv);
    // grid = 2048: even bids -> 1024 reduce/softmax blocks, odd -> 1024 V blocks
    attn_out_kernel<<<NB * NP * NS, 256>>>(out);
}

// round 4
// speedup vs baseline: 1.1030x; 1.0289x over previous
#include <cuda_runtime.h>
#include <cstddef>

#define NP 4
#define NS 4
#define NC 64
#define NF 64
#define NB 64
// PS = 16, PSC = 1024, per-psc KQ block = F*C*F = 262144 floats

__device__ float g_weights[NP * NS * NC * NC];           // softmax(scores), 256 KB
__device__ float g_V[NB * NP * NS * NC * NF];            // V = X @ Wv^T, 16 MB

// ---------------------------------------------------------------------------
// Combined kernel: 2048 blocks x 1024 threads, roles interleaved by bid&1.
//
// EVEN blocks (psc = bid>>1): KQ reduction (DRAM-roofline) + fused softmax.
// ODD  blocks (bp  = bid>>1): V[bp] = X[bp] @ Wv^T, vectorized LDS/STG so it
//   rides in the idle issue slots of the DRAM-bound reduce blocks.
// ---------------------------------------------------------------------------
__global__ void __launch_bounds__(1024, 2)
reduce_softmax_v_kernel(const float* __restrict__ kq,
                        const float* __restrict__ x,
                        const float* __restrict__ wv) {
    __shared__ float sh[NC * (NF + 1) + NC * (NF + 4)];  // 34 KB union

    const int bid = blockIdx.x;
    const int t   = threadIdx.x;

    if ((bid & 1) == 0) {
        // ---- role A: KQ reduction + softmax ----
        const int psc = bid >> 1;
        const int d   = t >> 4;
        const int j   = t & 15;

        const float4* base =
            reinterpret_cast<const float4*>(kq + (size_t)psc * (NF * NC * NF))
            + (d * (NF / 4) + j);

        float4 acc = make_float4(0.f, 0.f, 0.f, 0.f);
#pragma unroll 4
        for (int f = 0; f < NF; ++f) {
            float4 v = __ldcs(base + f * (NC * NF / 4));
            acc.x += v.x; acc.y += v.y; acc.z += v.z; acc.w += v.w;
        }
        float s = (acc.x + acc.y) + (acc.z + acc.w);

        s += __shfl_xor_sync(0xffffffffu, s, 8);
        s += __shfl_xor_sync(0xffffffffu, s, 4);
        s += __shfl_xor_sync(0xffffffffu, s, 2);
        s += __shfl_xor_sync(0xffffffffu, s, 1);

        if (j == 0) sh[d] = s;
        __syncthreads();

        if (t < 32) {
            const float a = sh[t];
            const float b = sh[t + 32];
            float m = fmaxf(a, b);
#pragma unroll
            for (int off = 16; off > 0; off >>= 1)
                m = fmaxf(m, __shfl_xor_sync(0xffffffffu, m, off));
            const float ea = __expf(a - m);
            const float eb = __expf(b - m);
            float ssum = ea + eb;
#pragma unroll
            for (int off = 16; off > 0; off >>= 1)
                ssum += __shfl_xor_sync(0xffffffffu, ssum, off);
            const float inv = 1.0f / ssum;
            g_weights[psc * NC + t]      = ea * inv;
            g_weights[psc * NC + t + 32] = eb * inv;
        }
    } else {
        // ---- role B: V = X @ Wv^T for one (b,ps), float4-vectorized ----
        const int bp = bid >> 1;                    // = b*16 + ps
        float* bufX  = sh;                          // [64][65] : X[c][k]
        float* bufWT = sh + NC * (NF + 1);          // [64][68] : Wv^T[k][f]

        // load X tile (coalesced) and Wv transposed
        const float* xsrc = x + (size_t)bp * (NC * NF);
#pragma unroll
        for (int r = 0; r < 4; ++r) {
            const int idx = t + r * 1024;
            const int hi  = idx >> 6, lo = idx & 63;
            bufX[hi * (NF + 1) + lo] = xsrc[idx];
            bufWT[lo * (NF + 4) + hi] = wv[idx];    // wv[f][k] -> bufWT[k][f]
        }
        __syncthreads();

        // thread t: c = t>>4 (0..63), fq = t&15 -> V[c][4fq..4fq+3]
        const int c  = t >> 4;
        const int fq = t & 15;
        float4 acc = make_float4(0.f, 0.f, 0.f, 0.f);
#pragma unroll 8
        for (int k = 0; k < NF; ++k) {
            const float  xk = bufX[c * (NF + 1) + k];
            const float4 w4 = *reinterpret_cast<const float4*>(
                                  &bufWT[k * (NF + 4) + 4 * fq]);
            acc.x += xk * w4.x; acc.y += xk * w4.y;
            acc.z += xk * w4.z; acc.w += xk * w4.w;
        }

        float4* vdst = reinterpret_cast<float4*>(g_V + (size_t)bp * (NC * NF));
        vdst[c * (NF / 4) + fq] = acc;
    }
}

// ---------------------------------------------------------------------------
// Kernel 2: out[b,ps][c][f] = sum_d w[ps][c][d] * V[b,ps][d][f]
// 1024 blocks (b*16+ps) x 256 threads.
// Thread (tc=t>>4, tf=t&15): 4 c-rows (tc+16i) x one contiguous f-float4
// (4tf..4tf+3). Inner loop over d in chunks of 4:
//   4 LDS.128 of w[c_i][4d..] (float4 along d, row-padded to 68 floats)
// + 4 LDS.128 of V[4d+q][4tf..] (float4 along f)
// -> 8 LDS.128 per 64 FFMA (was 32 LDS.32): 4x less smem traffic.
// ---------------------------------------------------------------------------
__global__ void __launch_bounds__(256)
attn_out_kernel(float* __restrict__ out) {
    __shared__ float bufV[NC * NF];         // V[d][f], flat, rows contiguous
    __shared__ float bufW[NC * (NF + 4)];   // w[c][d], stride 68 (16B-aligned)

    const int blk = blockIdx.x;
    const int b   = blk >> 4;
    const int ps  = blk & 15;
    const int t   = threadIdx.x;
    const int tc  = t >> 4;
    const int tf  = t & 15;

    const float4* vsrc = reinterpret_cast<const float4*>(g_V + (size_t)blk * (NC * NF));
    const float4* wsrc = reinterpret_cast<const float4*>(g_weights + (size_t)ps * (NC * NC));
    float4* bv4 = reinterpret_cast<float4*>(bufV);
#pragma unroll
    for (int r = 0; r < 4; ++r) {
        const int i4 = t + r * 256;                  // 0..1023 float4s
        bv4[i4] = vsrc[i4];
        // w row = i4>>4 (16 float4 per 64-wide row), col4 = i4&15
        reinterpret_cast<float4*>(&bufW[(i4 >> 4) * (NF + 4)])[i4 & 15] = wsrc[i4];
    }
    __syncthreads();

    float4 o0 = make_float4(0.f, 0.f, 0.f, 0.f);
    float4 o1 = o0, o2 = o0, o3 = o0;

#pragma unroll 4
    for (int d4 = 0; d4 < NC / 4; ++d4) {
        // V rows for d = 4*d4 .. 4*d4+3, f-slice [4tf, 4tf+4)
        const float4 v0 = *reinterpret_cast<const float4*>(&bufV[(4 * d4 + 0) * NF + 4 * tf]);
        const float4 v1 = *reinterpret_cast<const float4*>(&bufV[(4 * d4 + 1) * NF + 4 * tf]);
        const float4 v2 = *reinterpret_cast<const float4*>(&bufV[(4 * d4 + 2) * NF + 4 * tf]);
        const float4 v3 = *reinterpret_cast<const float4*>(&bufV[(4 * d4 + 3) * NF + 4 * tf]);

#pragma unroll
        for (int i = 0; i < 4; ++i) {
            const float4 w4 = *reinterpret_cast<const float4*>(
                                  &bufW[(tc + 16 * i) * (NF + 4) + 4 * d4]);
            float4& o = (i == 0) ? o0 : (i == 1) ? o1 : (i == 2) ? o2 : o3;
            o.x += w4.x * v0.x + w4.y * v1.x + w4.z * v2.x + w4.w * v3.x;
            o.y += w4.x * v0.y + w4.y * v1.y + w4.z * v2.y + w4.w * v3.y;
            o.z += w4.x * v0.z + w4.y * v1.z + w4.z * v2.z + w4.w * v3.z;
            o.w += w4.x * v0.w + w4.y * v1.w + w4.z * v2.w + w4.w * v3.w;
        }
    }

    // out layout: (C, B, P*S*F); out[c, b, ps*F + f], f-slice [4tf, 4tf+4)
#pragma unroll
    for (int i = 0; i < 4; ++i) {
        const int c = tc + 16 * i;
        float* orow = out + ((size_t)c * NB + b) * (NP * NS * NF) + (size_t)ps * NF;
        const float4 o = (i == 0) ? o0 : (i == 1) ? o1 : (i == 2) ? o2 : o3;
        *reinterpret_cast<float4*>(&orow[4 * tf]) = o;
    }
}

// ---------------------------------------------------------------------------
extern "C" void kernel_launch(void* const* d_in, const int* in_sizes, int n_in,
                              void* d_out, int out_size) {
    const float* X  = (const float*)d_in[0];  // (B, P*S*C*F)
    const float* KQ = (const float*)d_in[1];  // (P,S,C,F,C,F) — 1 GB
    const float* Wv = (const float*)d_in[2];  // (F, F)
    float* out = (float*)d_out;               // (C, B, P*S*F)

    reduce_softmax_v_kernel<<<2048, 1024>>>(KQ, X, Wv);
    attn_out_kernel<<<NB * NP * NS, 256>>>(out);
}